// round 14
// baseline (speedup 1.0000x reference)
#include <cuda_runtime.h>
#include <cuda_bf16.h>

// Problem constants (reference: B=32, A=4096, P=8388608, E=8)
#define Bn 32
#define An 4096
#define En 8

#define PT 256
#define PREFIX 16384          // shared pair prefix scanned by every block
#define CH 65536              // fallback chunk (pairs) for unresolved blocks

// Exact pair test for a FIXED structure (base_atom = b*An).
__device__ __forceinline__ int close_pair(const float* __restrict__ pos,
                                          const int* __restrict__ elm,
                                          const float* s_rad,
                                          int base_atom, int i, int j) {
    int ai = base_atom + i;
    int aj = base_atom + j;
    float ax = __ldg(pos + 3 * ai + 0);
    float ay = __ldg(pos + 3 * ai + 1);
    float az = __ldg(pos + 3 * ai + 2);
    float bx = __ldg(pos + 3 * aj + 0);
    float by = __ldg(pos + 3 * aj + 1);
    float bz = __ldg(pos + 3 * aj + 2);
    float rs = s_rad[__ldg(elm + ai) & 7] + s_rad[__ldg(elm + aj) & 7];
    float dx = bx - ax, dy = by - ay, dz = bz - az;
    float sod = dx * dx + dy * dy + dz * dz;
    return (rs * rs >= sod) ? 1 : 0;
}

// ---------------------------------------------------------------------------
// ONE kernel, 33 blocks, ZERO cross-block communication.
// Block b (<32) is the single owner/writer of out[b]:
//   resolved(b) = eng_big(b)  OR  any too-close pair with n==b.
// It checks eng_big exactly, filters the shared 16K-pair prefix for n==b
// (~512 candidates; P(all miss) ~ e^-60), and only if still unresolved
// chunk-scans the rest of the pair list for its structure (exact fallback).
// Block 32 zero-fills the out tail.
__global__ void __launch_bounds__(PT)
k_all(const float* __restrict__ pos,
      const float* __restrict__ eng,
      const int* __restrict__ elm,
      const float* __restrict__ radius,
      const float* __restrict__ eng_atm,
      const int* __restrict__ nn,
      const int* __restrict__ ii,
      const int* __restrict__ jj,
      int P,
      float* __restrict__ out, int out_size) {
    const int b   = blockIdx.x;
    const int tid = threadIdx.x;

    if (b >= Bn) {                       // tail-zero block
        for (int x = Bn + tid; x < out_size; x += PT) out[x] = 0.0f;
        return;
    }

    __shared__ float s_atm[En];
    __shared__ float s_rad[En];
    __shared__ float s_red[PT / 32];
    __shared__ float s_tot;

    if (tid < En) { s_atm[tid] = eng_atm[tid]; s_rad[tid] = radius[tid]; }
    __syncthreads();

    const int base_atom = b * An;
    int local = 0;

    // ---- engmax for structure b (coalesced int4 over its elm row) ----
    {
        const int4* row = (const int4*)(elm + base_atom);
        float s = 0.f;
        #pragma unroll
        for (int t = 0; t < An / (PT * 4); ++t) {   // 4 int4 per thread
            int4 e4 = __ldg(row + tid + t * PT);
            s += s_atm[e4.x & 7] + s_atm[e4.y & 7]
               + s_atm[e4.z & 7] + s_atm[e4.w & 7];
        }
        #pragma unroll
        for (int o = 16; o > 0; o >>= 1)
            s += __shfl_down_sync(0xFFFFFFFFu, s, o);
        if ((tid & 31) == 0) s_red[tid >> 5] = s;
        __syncthreads();
        if (tid == 0) {
            float tot = 0.f;
            #pragma unroll
            for (int w = 0; w < PT / 32; ++w) tot += s_red[w];
            s_tot = tot;
        }
        __syncthreads();
        if (tid == 0 && __ldg(eng + b) >= s_tot) local = 1;
    }

    // ---- prefix filter: scan n[0..PREFIX) for n==b, evaluate matches ----
    {
        const int pend = (PREFIX < P) ? PREFIX : P;
        const int4* n4p = (const int4*)nn;
        for (int idx = tid * 4; idx + 4 <= pend; idx += PT * 4) {
            int4 n4 = __ldg(n4p + (idx >> 2));
            if (n4.x == b)
                local |= close_pair(pos, elm, s_rad, base_atom,
                                    __ldg(ii + idx + 0), __ldg(jj + idx + 0));
            if (n4.y == b)
                local |= close_pair(pos, elm, s_rad, base_atom,
                                    __ldg(ii + idx + 1), __ldg(jj + idx + 1));
            if (n4.z == b)
                local |= close_pair(pos, elm, s_rad, base_atom,
                                    __ldg(ii + idx + 2), __ldg(jj + idx + 2));
            if (n4.w == b)
                local |= close_pair(pos, elm, s_rad, base_atom,
                                    __ldg(ii + idx + 3), __ldg(jj + idx + 3));
        }
        // scalar tail (only if P < PREFIX and unaligned)
        for (int idx = (pend & ~3) + tid; idx < pend; idx += PT)
            if (__ldg(nn + idx) == b)
                local |= close_pair(pos, elm, s_rad, base_atom,
                                    __ldg(ii + idx), __ldg(jj + idx));
    }

    // ---- block-uniform resolution; no shared-flag races ----
    int resolved = __syncthreads_or(local);

    // ---- exact fallback (statistically never taken): continue scanning
    // this structure's pairs in chunks until a hit or the end of the list.
    long long basep = PREFIX;
    while (!resolved && basep < (long long)P) {
        long long cend = basep + CH;
        if (cend > (long long)P) cend = (long long)P;
        int l2 = 0;
        for (long long idx = basep + tid * 4; idx + 4 <= cend; idx += PT * 4) {
            int4 n4 = __ldg((const int4*)(nn + idx));
            if (n4.x == b)
                l2 |= close_pair(pos, elm, s_rad, base_atom,
                                 __ldg(ii + idx + 0), __ldg(jj + idx + 0));
            if (n4.y == b)
                l2 |= close_pair(pos, elm, s_rad, base_atom,
                                 __ldg(ii + idx + 1), __ldg(jj + idx + 1));
            if (n4.z == b)
                l2 |= close_pair(pos, elm, s_rad, base_atom,
                                 __ldg(ii + idx + 2), __ldg(jj + idx + 2));
            if (n4.w == b)
                l2 |= close_pair(pos, elm, s_rad, base_atom,
                                 __ldg(ii + idx + 3), __ldg(jj + idx + 3));
        }
        for (long long idx = (cend & ~3LL) + tid; idx < cend; idx += PT)
            if (__ldg(nn + idx) == b)
                l2 |= close_pair(pos, elm, s_rad, base_atom,
                                 __ldg(ii + idx), __ldg(jj + idx));
        resolved = __syncthreads_or(l2);
        basep += CH;
    }

    // ---- single writer for out[b] ----
    if (tid == 0) out[b] = resolved ? 1.0f : 0.0f;
}

// ---------------------------------------------------------------------------
// Inputs (metadata order): pos[B,A,3] f32, eng[B] f32, elm[B,A] i32,
// radius[E] f32, eng_atm[E] f32, n[P] i32, i[P] i32, j[P] i32.
// Output: float32[B] (0.0 / 1.0).
// ONE graph node; no device-global state; no atomics; single writer per
// output element => deterministic and replay-safe by construction.
extern "C" void kernel_launch(void* const* d_in, const int* in_sizes, int n_in,
                              void* d_out, int out_size) {
    const float* pos     = (const float*)d_in[0];
    const float* eng     = (const float*)d_in[1];
    const int*   elm     = (const int*)d_in[2];
    const float* radius  = (const float*)d_in[3];
    const float* eng_atm = (const float*)d_in[4];
    const int*   nn      = (const int*)d_in[5];
    const int*   ii      = (const int*)d_in[6];
    const int*   jj      = (const int*)d_in[7];
    int P = in_sizes[5];

    k_all<<<Bn + 1, PT>>>(pos, eng, elm, radius, eng_atm, nn, ii, jj, P,
                          (float*)d_out, out_size);
}

// round 15
// speedup vs baseline: 2.3677x; 2.3677x over previous
#include <cuda_runtime.h>
#include <cuda_bf16.h>

// Problem constants (reference: B=32, A=4096, P=8388608, E=8)
#define Bn 32
#define An 4096
#define En 8

#define PT 256
#define PREFIX 8192           // shared pair prefix (expected ~256 matches/block)
#define MAXC 1024             // compaction buffer capacity (4 KB smem)
#define CH 65536              // fallback chunk size (pairs)

// Exact pair test for a FIXED structure (base_atom = b*An).
__device__ __forceinline__ int close_pair(const float* __restrict__ pos,
                                          const int* __restrict__ elm,
                                          const float* s_rad,
                                          int base_atom, int i, int j) {
    int ai = base_atom + i;
    int aj = base_atom + j;
    float ax = __ldg(pos + 3 * ai + 0);
    float ay = __ldg(pos + 3 * ai + 1);
    float az = __ldg(pos + 3 * ai + 2);
    float bx = __ldg(pos + 3 * aj + 0);
    float by = __ldg(pos + 3 * aj + 1);
    float bz = __ldg(pos + 3 * aj + 2);
    float rs = s_rad[__ldg(elm + ai) & 7] + s_rad[__ldg(elm + aj) & 7];
    float dx = bx - ax, dy = by - ay, dz = bz - az;
    float sod = dx * dx + dy * dy + dz * dz;
    return (rs * rs >= sod) ? 1 : 0;
}

// ---------------------------------------------------------------------------
// ONE kernel, 33 blocks, zero cross-block communication. Block b (<32) owns
// out[b] = eng_big(b) OR too_close(b).
//   Phase E: engmax reduction (coalesced int4 stream).
//   Phase 1: stream the shared n-prefix, COMPACT n==b matches to smem
//            (no gathers inside the scan loop).
//   Phase 2: dense evaluation of compacted candidates (all threads, one
//            high-MLP gather round).
//   Fallback (statistically never): chunked inline scan of remaining pairs;
//   re-covers the prefix if the compaction buffer overflowed.
// Block 32 zero-fills the out tail.
__global__ void __launch_bounds__(PT)
k_all(const float* __restrict__ pos,
      const float* __restrict__ eng,
      const int* __restrict__ elm,
      const float* __restrict__ radius,
      const float* __restrict__ eng_atm,
      const int* __restrict__ nn,
      const int* __restrict__ ii,
      const int* __restrict__ jj,
      int P,
      float* __restrict__ out, int out_size) {
    const int b   = blockIdx.x;
    const int tid = threadIdx.x;

    if (b >= Bn) {                       // tail-zero block
        for (int x = Bn + tid; x < out_size; x += PT) out[x] = 0.0f;
        return;
    }

    __shared__ float s_atm[En];
    __shared__ float s_rad[En];
    __shared__ float s_red[PT / 32];
    __shared__ int   s_idx[MAXC];
    __shared__ int   s_cnt;

    if (tid < En) { s_atm[tid] = eng_atm[tid]; s_rad[tid] = radius[tid]; }
    if (tid == 0) s_cnt = 0;
    __syncthreads();

    const int base_atom = b * An;
    int local = 0;

    // ---- Phase E: engmax for structure b ----
    {
        const int4* row = (const int4*)(elm + base_atom);
        float s = 0.f;
        #pragma unroll
        for (int t = 0; t < An / (PT * 4); ++t) {   // 4 int4 per thread
            int4 e4 = __ldg(row + tid + t * PT);
            s += s_atm[e4.x & 7] + s_atm[e4.y & 7]
               + s_atm[e4.z & 7] + s_atm[e4.w & 7];
        }
        #pragma unroll
        for (int o = 16; o > 0; o >>= 1)
            s += __shfl_down_sync(0xFFFFFFFFu, s, o);
        if ((tid & 31) == 0) s_red[tid >> 5] = s;
        __syncthreads();
        if (tid == 0) {
            float tot = 0.f;
            #pragma unroll
            for (int w = 0; w < PT / 32; ++w) tot += s_red[w];
            if (__ldg(eng + b) >= tot) local = 1;
        }
    }

    // ---- Phase 1: stream n-prefix, compact matches (pure streaming) ----
    const int pend = (PREFIX < P) ? PREFIX : P;
    {
        const int4* n4p = (const int4*)nn;
        for (int idx = tid * 4; idx + 4 <= pend; idx += PT * 4) {
            int4 n4 = __ldg(n4p + (idx >> 2));
            if (n4.x == b) { int p = atomicAdd(&s_cnt, 1); if (p < MAXC) s_idx[p] = idx + 0; }
            if (n4.y == b) { int p = atomicAdd(&s_cnt, 1); if (p < MAXC) s_idx[p] = idx + 1; }
            if (n4.z == b) { int p = atomicAdd(&s_cnt, 1); if (p < MAXC) s_idx[p] = idx + 2; }
            if (n4.w == b) { int p = atomicAdd(&s_cnt, 1); if (p < MAXC) s_idx[p] = idx + 3; }
        }
        for (int idx = (pend & ~3) + tid; idx < pend; idx += PT)
            if (__ldg(nn + idx) == b) {
                int p = atomicAdd(&s_cnt, 1);
                if (p < MAXC) s_idx[p] = idx;
            }
    }
    __syncthreads();

    // ---- Phase 2: dense evaluation (one parallel gather round) ----
    const int cnt = (s_cnt < MAXC) ? s_cnt : MAXC;
    for (int t = tid; t < cnt; t += PT) {
        int q = s_idx[t];
        local |= close_pair(pos, elm, s_rad, base_atom,
                            __ldg(ii + q), __ldg(jj + q));
    }

    int resolved = __syncthreads_or(local);

    // ---- Exact fallback (statistically never taken). If the compaction
    // buffer overflowed, re-cover the prefix too.
    long long basep = (s_cnt > MAXC) ? 0 : (long long)pend;
    while (!resolved && basep < (long long)P) {
        long long cend = basep + CH;
        if (cend > (long long)P) cend = (long long)P;
        int l2 = 0;
        for (long long idx = basep + tid * 4; idx + 4 <= cend; idx += PT * 4) {
            int4 n4 = __ldg((const int4*)(nn + idx));
            if (n4.x == b)
                l2 |= close_pair(pos, elm, s_rad, base_atom,
                                 __ldg(ii + idx + 0), __ldg(jj + idx + 0));
            if (n4.y == b)
                l2 |= close_pair(pos, elm, s_rad, base_atom,
                                 __ldg(ii + idx + 1), __ldg(jj + idx + 1));
            if (n4.z == b)
                l2 |= close_pair(pos, elm, s_rad, base_atom,
                                 __ldg(ii + idx + 2), __ldg(jj + idx + 2));
            if (n4.w == b)
                l2 |= close_pair(pos, elm, s_rad, base_atom,
                                 __ldg(ii + idx + 3), __ldg(jj + idx + 3));
        }
        for (long long idx = (cend & ~3LL) + tid; idx < cend; idx += PT)
            if (__ldg(nn + idx) == b)
                l2 |= close_pair(pos, elm, s_rad, base_atom,
                                 __ldg(ii + idx), __ldg(jj + idx));
        resolved = __syncthreads_or(l2);
        basep += CH;
    }

    // ---- single writer for out[b] ----
    if (tid == 0) out[b] = resolved ? 1.0f : 0.0f;
}

// ---------------------------------------------------------------------------
// Inputs (metadata order): pos[B,A,3] f32, eng[B] f32, elm[B,A] i32,
// radius[E] f32, eng_atm[E] f32, n[P] i32, i[P] i32, j[P] i32.
// Output: float32[B] (0.0 / 1.0).
// ONE graph node; no device-global state; no global atomics; single writer
// per output element => deterministic and replay-safe by construction.
extern "C" void kernel_launch(void* const* d_in, const int* in_sizes, int n_in,
                              void* d_out, int out_size) {
    const float* pos     = (const float*)d_in[0];
    const float* eng     = (const float*)d_in[1];
    const int*   elm     = (const int*)d_in[2];
    const float* radius  = (const float*)d_in[3];
    const float* eng_atm = (const float*)d_in[4];
    const int*   nn      = (const int*)d_in[5];
    const int*   ii      = (const int*)d_in[6];
    const int*   jj      = (const int*)d_in[7];
    int P = in_sizes[5];

    k_all<<<Bn + 1, PT>>>(pos, eng, elm, radius, eng_atm, nn, ii, jj, P,
                          (float*)d_out, out_size);
}

// round 16
// speedup vs baseline: 2.7623x; 1.1667x over previous
#include <cuda_runtime.h>
#include <cuda_bf16.h>

// Problem constants (reference: B=32, A=4096, P=8388608, E=8)
#define Bn 32
#define An 4096
#define En 8

#define PT 256
#define ENG_BLK Bn                 // blocks 0..31: engmax
#define PAIR_BLK 64                // blocks 32..95: pair scan
#define NBLK (ENG_BLK + PAIR_BLK)  // 96
#define WPB (PT / 32)              // 8 warps/block
#define NPW (PAIR_BLK * WPB)       // 512 pair warps
#define PREFIX (NPW * 32)          // 16384 pairs in stage A (1 per lane)
#define WTILE 128                  // fallback tile

// Device state. Zero at module load; the last-ticket block resets both after
// all publishers are provably done, so every graph replay starts clean.
__device__ unsigned g_done;        // resolved bits (fallback detector only)
__device__ unsigned g_count;       // completion ticket

__device__ __forceinline__ unsigned poll_u32(const unsigned* p) {
    unsigned v;
    asm volatile("ld.global.cg.u32 %0, [%1];" : "=r"(v) : "l"(p) : "memory");
    return v;
}

// Exact pair test; returns (1u<<n) if too close, else 0.
__device__ __forceinline__ unsigned pair_bit(const float* __restrict__ pos,
                                             const int* __restrict__ elm,
                                             const float* s_rad,
                                             int nb, int i, int j) {
    int ai = nb * An + i;
    int aj = nb * An + j;
    float ax = __ldg(pos + 3 * ai + 0);
    float ay = __ldg(pos + 3 * ai + 1);
    float az = __ldg(pos + 3 * ai + 2);
    float bx = __ldg(pos + 3 * aj + 0);
    float by = __ldg(pos + 3 * aj + 1);
    float bz = __ldg(pos + 3 * aj + 2);
    float rs = s_rad[__ldg(elm + ai) & 7] + s_rad[__ldg(elm + aj) & 7];
    float dx = bx - ax, dy = by - ay, dz = bz - az;
    float sod = dx * dx + dy * dy + dz * dz;
    return (rs * rs >= sod) ? (1u << nb) : 0u;
}

// ---------------------------------------------------------------------------
// One kernel node after a memset node. 96 flat blocks:
//   blocks 0..31  : engmax for structure b; on eng_big store out[b]=1.0f.
//   blocks 32..95 : 1 pair/lane over the 16384-pair prefix; on hit store
//                   out[nb]=1.0f.
// All stores write the SAME value (1.0f) over a memset-zeroed buffer =>
// deterministic regardless of ordering. g_done bits are maintained only to
// DETECT the (statistically impossible) unresolved case; nobody spins — the
// last-ticket block alone checks, and runs the exact fallback if needed.
__global__ void __launch_bounds__(PT)
k_scan(const float* __restrict__ pos,
       const float* __restrict__ eng,
       const int* __restrict__ elm,
       const float* __restrict__ radius,
       const float* __restrict__ eng_atm,
       const int* __restrict__ nn,
       const int* __restrict__ ii,
       const int* __restrict__ jj,
       int P,
       float* __restrict__ out) {
    __shared__ float s_rad[En];
    __shared__ unsigned s_ticket;

    const int tid = threadIdx.x;
    const int bid = blockIdx.x;
    const int lane = tid & 31;
    const int wid = tid >> 5;

    if (tid < En) s_rad[tid] = radius[tid];

    if (bid < ENG_BLK) {
        // ---- engmax for structure `bid` (flat, coalesced) ----
        __shared__ float s_atm[En];
        __shared__ float s_red[PT / 32];
        if (tid < En) s_atm[tid] = eng_atm[tid];
        __syncthreads();

        const int4* row = (const int4*)(elm + bid * An);
        float s = 0.f;
        #pragma unroll
        for (int t = 0; t < An / (PT * 4); ++t) {   // 4 int4 per thread
            int4 e4 = __ldg(row + tid + t * PT);
            s += s_atm[e4.x & 7] + s_atm[e4.y & 7]
               + s_atm[e4.z & 7] + s_atm[e4.w & 7];
        }
        #pragma unroll
        for (int o = 16; o > 0; o >>= 1)
            s += __shfl_down_sync(0xFFFFFFFFu, s, o);
        if ((tid & 31) == 0) s_red[tid >> 5] = s;
        __syncthreads();
        if (tid == 0) {
            float tot = 0.f;
            #pragma unroll
            for (int w = 0; w < PT / 32; ++w) tot += s_red[w];
            if (__ldg(eng + bid) >= tot) {
                out[bid] = 1.0f;                    // same-value store
                atomicOr(&g_done, 1u << bid);       // RED (detector)
            }
        }
    } else {
        // ---- pair scan: one pair per lane over the global prefix ----
        __syncthreads();
        const int gw = (bid - ENG_BLK) * WPB + wid;
        int q = gw * 32 + lane;
        unsigned local = 0u;
        int nb = 0;
        if (q < P) {
            nb = __ldg(nn + q);
            local = pair_bit(pos, elm, s_rad, nb, __ldg(ii + q), __ldg(jj + q));
        }
        if (local) out[nb] = 1.0f;                  // same-value store
        unsigned wbits = __reduce_or_sync(0xFFFFFFFFu, local);
        if (wbits && lane == 0) atomicOr(&g_done, wbits);   // RED (detector)
    }

    // ---- Spin-free ticket (threadfence-reduction pattern). Everyone exits;
    // only the LAST block checks the detector.
    __threadfence();                 // each thread orders its own stores/REDs
    __syncthreads();
    if (tid == 0) s_ticket = atomicAdd(&g_count, 1u);
    __syncthreads();
    if (s_ticket != (unsigned)(NBLK - 1)) return;   // no waiting

    // ---- Last block only. All prior REDs/stores are visible.
    unsigned m = poll_u32(&g_done);

    if (m != 0xFFFFFFFFu) {
        // ======== exact fallback (statistically never taken) ========
        // Scan [PREFIX, P) with this block's 8 warps; write hits directly.
        const long long ntiles =
            ((long long)P - PREFIX + WTILE - 1) / WTILE;
        __shared__ unsigned s_m;
        if (tid == 0) s_m = m;
        __syncthreads();
        for (long long t = wid; t < ntiles; t += WPB) {
            m = s_m;
            if (m == 0xFFFFFFFFu) break;
            long long idx = (long long)PREFIX + t * WTILE + lane * 4;
            unsigned local = 0u;
            if (idx + 4 <= (long long)P) {
                int4 n4 = __ldg((const int4*)(nn + idx));
                int4 i4 = __ldg((const int4*)(ii + idx));
                int4 j4 = __ldg((const int4*)(jj + idx));
                int na[4] = {n4.x, n4.y, n4.z, n4.w};
                int ia[4] = {i4.x, i4.y, i4.z, i4.w};
                int ja[4] = {j4.x, j4.y, j4.z, j4.w};
                #pragma unroll
                for (int k = 0; k < 4; ++k) {
                    if ((m >> na[k]) & 1u) continue;
                    unsigned bit = pair_bit(pos, elm, s_rad,
                                            na[k], ia[k], ja[k]);
                    if (bit) out[na[k]] = 1.0f;
                    local |= bit;
                }
            } else if (idx < (long long)P) {
                for (int k = 0; k < 4; ++k) {
                    long long q = idx + k;
                    if (q >= (long long)P) break;
                    int nb2 = __ldg(nn + q);
                    if ((m >> nb2) & 1u) continue;
                    unsigned bit = pair_bit(pos, elm, s_rad, nb2,
                                            __ldg(ii + q), __ldg(jj + q));
                    if (bit) out[nb2] = 1.0f;
                    local |= bit;
                }
            }
            unsigned wbits = __reduce_or_sync(0xFFFFFFFFu, local) & ~m;
            if (wbits && lane == 0) atomicOr(&s_m, wbits);
        }
        __syncthreads();
    }

    // ---- reset device state for the next replay (all publishers done).
    if (tid == 0) { g_done = 0u; g_count = 0u; }
}

// ---------------------------------------------------------------------------
// Inputs (metadata order): pos[B,A,3] f32, eng[B] f32, elm[B,A] i32,
// radius[E] f32, eng_atm[E] f32, n[P] i32, i[P] i32, j[P] i32.
// Output: float32[B] (0.0 / 1.0).
// Graph: memset(d_out, 0) -> k_scan. Zeros come from the memset; every
// kernel store writes 1.0f => order-independent, replay-deterministic.
extern "C" void kernel_launch(void* const* d_in, const int* in_sizes, int n_in,
                              void* d_out, int out_size) {
    const float* pos     = (const float*)d_in[0];
    const float* eng     = (const float*)d_in[1];
    const int*   elm     = (const int*)d_in[2];
    const float* radius  = (const float*)d_in[3];
    const float* eng_atm = (const float*)d_in[4];
    const int*   nn      = (const int*)d_in[5];
    const int*   ii      = (const int*)d_in[6];
    const int*   jj      = (const int*)d_in[7];
    int P = in_sizes[5];

    cudaMemsetAsync(d_out, 0, (size_t)out_size * sizeof(float));
    k_scan<<<NBLK, PT>>>(pos, eng, elm, radius, eng_atm, nn, ii, jj, P,
                         (float*)d_out);
}